// round 3
// baseline (speedup 1.0000x reference)
#include <cuda_runtime.h>
#include <cstdint>

#define N_NODES     500000
#define N_INC       2000000
#define N_HEDGES    100000
#define N_GRAPHS    512
#define CH          64
#define FULLM       0xffffffffu

// ---------------- scratch (device globals; no allocation allowed) ----------------
__device__ __align__(256) float g_m [(long)N_HEDGES * CH];   // 25.6 MB
__device__ __align__(256) float g_m2[(long)N_HEDGES * CH];   // 25.6 MB
__device__ int   g_degN[N_NODES];
__device__ int   g_degE[N_HEDGES];
__device__ float g_binv[N_HEDGES];
__device__ float g_dinv[N_NODES];
__device__ int   g_rowptr[N_NODES + 1];
__device__ int   g_cursor[N_NODES];
__device__ int   g_csr[N_INC];
__device__ int   g_bsums[512];
__device__ float g_gsum[N_GRAPHS];
__device__ int   g_gcnt[N_GRAPHS];

// ---------------- packed f32x2 helpers ----------------
__device__ __forceinline__ unsigned long long pk2(float v) {
    unsigned long long r;
    asm("mov.b64 %0, {%1, %1};" : "=l"(r) : "f"(v));
    return r;
}
__device__ __forceinline__ unsigned long long pkab(float a, float b) {
    unsigned long long r;
    asm("mov.b64 %0, {%1, %2};" : "=l"(r) : "f"(a), "f"(b));
    return r;
}
__device__ __forceinline__ float2 upk(unsigned long long v) {
    float2 r;
    asm("mov.b64 {%0, %1}, %2;" : "=f"(r.x), "=f"(r.y) : "l"(v));
    return r;
}
__device__ __forceinline__ void fma2(unsigned long long& acc, unsigned long long a, unsigned long long b) {
    asm("fma.rn.f32x2 %0, %1, %2, %0;" : "+l"(acc) : "l"(a), "l"(b));
}
__device__ __forceinline__ void red4(float* p, float a, float b, float c, float d) {
    asm volatile("red.global.add.v4.f32 [%0], {%1, %2, %3, %4};"
                 :: "l"(p), "f"(a), "f"(b), "f"(c), "f"(d) : "memory");
}

// ---------------- zero scratch ----------------
__global__ void k_zero() {
    long t = (long)blockIdx.x * blockDim.x + threadIdx.x;
    long S = (long)gridDim.x * blockDim.x;
    float4 z4 = make_float4(0.f, 0.f, 0.f, 0.f);
    float4* m4 = (float4*)g_m;
    float4* n4 = (float4*)g_m2;
    const long M4 = (long)N_HEDGES * CH / 4;
    for (long j = t; j < M4; j += S) { m4[j] = z4; n4[j] = z4; }
    for (long j = t; j < N_NODES; j += S) { g_degN[j] = 0; g_cursor[j] = 0; }
    for (long j = t; j < N_HEDGES; j += S) g_degE[j] = 0;
    for (long j = t; j < N_GRAPHS; j += S) { g_gsum[j] = 0.f; g_gcnt[j] = 0; }
}

// ---------------- degree histograms + graph-size histogram ----------------
__global__ void k_hist(const int* __restrict__ row, const int* __restrict__ col,
                       const int* __restrict__ batch) {
    int i = blockIdx.x * blockDim.x + threadIdx.x;
    if (i < N_INC) {
        atomicAdd(&g_degN[row[i]], 1);
        atomicAdd(&g_degE[col[i]], 1);
    }
    unsigned act = __ballot_sync(FULLM, i < N_NODES);
    if (i < N_NODES) {
        int g = batch[i];
        unsigned mask = __match_any_sync(act, g);
        int leader = __ffs(mask) - 1;
        if ((threadIdx.x & 31) == leader) atomicAdd(&g_gcnt[g], __popc(mask));
    }
}

// ---------------- exclusive scan of g_degN -> g_rowptr ----------------
__global__ void k_scan1() {
    __shared__ int sh[1024];
    int tid = threadIdx.x;
    int i = blockIdx.x * 1024 + tid;
    int v = (i < N_NODES) ? g_degN[i] : 0;
    sh[tid] = v;
    __syncthreads();
#pragma unroll
    for (int off = 1; off < 1024; off <<= 1) {
        int t = (tid >= off) ? sh[tid - off] : 0;
        __syncthreads();
        sh[tid] += t;
        __syncthreads();
    }
    if (i < N_NODES) g_rowptr[i] = sh[tid] - v;
    if (tid == 1023) g_bsums[blockIdx.x] = sh[1023];
}

__global__ void k_scan2(int nblocks) {
    __shared__ int sh[512];
    int tid = threadIdx.x;
    int v = (tid < nblocks) ? g_bsums[tid] : 0;
    sh[tid] = v;
    __syncthreads();
#pragma unroll
    for (int off = 1; off < 512; off <<= 1) {
        int t = (tid >= off) ? sh[tid - off] : 0;
        __syncthreads();
        sh[tid] += t;
        __syncthreads();
    }
    if (tid < nblocks) g_bsums[tid] = sh[tid] - v;
}

// scan finalize + inverse degrees
__global__ void k_scan3() {
    int i = blockIdx.x * 1024 + threadIdx.x;
    if (i < N_NODES) {
        g_rowptr[i] += g_bsums[blockIdx.x];
        int d = g_degN[i];
        g_dinv[i] = d > 0 ? 1.f / (float)d : 0.f;
    }
    if (i == 0) g_rowptr[N_NODES] = N_INC;
    if (i < N_HEDGES) {
        int d = g_degE[i];
        g_binv[i] = d > 0 ? 1.f / (float)d : 0.f;
    }
}

// ---------------- fill CSR ----------------
__global__ void k_fill(const int* __restrict__ row, const int* __restrict__ col) {
    int i = blockIdx.x * blockDim.x + threadIdx.x;
    if (i < N_INC) {
        int r = row[i];
        int pos = g_rowptr[r] + atomicAdd(&g_cursor[r], 1);
        g_csr[pos] = col[i];
    }
}

// ---------------- scale m in place by binv ----------------
// NOTE: device-symbol selection MUST happen in device code. Passing (float4*)g_m
// from the host launch function takes the HOST shadow symbol's address (silently
// "works" on GB300 via ATS but scales host memory) — that was the round-2 bug.
__global__ void k_scale(int which) {
    float4* __restrict__ m4 = (float4*)(which ? g_m2 : g_m);
    int i = blockIdx.x * blockDim.x + threadIdx.x;   // N_HEDGES*16 float4s
    if (i < N_HEDGES * 16) {
        float bi = g_binv[i >> 4];
        float4 v = m4[i];
        v.x *= bi; v.y *= bi; v.z *= bi; v.w *= bi;
        m4[i] = v;
    }
}

// ---------------- warp matvec: 4 nodes, lane owns 4 channels, f32x2 accum ----------------
// group grp = lane>>4 owns nodes (base+2*grp, base+2*grp+1) with inputs xa, xb.
__device__ __forceinline__ void matvec4(const float4& xa, const float4& xb,
                                        const float* __restrict__ Ws,
                                        const float* __restrict__ bs,
                                        int grp, int c4,
                                        float fa[4], float fb[4]) {
    unsigned long long ta01 = pkab(bs[c4], bs[c4 + 1]);
    unsigned long long ta23 = pkab(bs[c4 + 2], bs[c4 + 3]);
    unsigned long long tb01 = ta01, tb23 = ta23;
#pragma unroll
    for (int kk = 0; kk < 16; kk++) {
        int src = (grp << 4) + kk;
        float a0 = __shfl_sync(FULLM, xa.x, src);
        float a1 = __shfl_sync(FULLM, xa.y, src);
        float a2 = __shfl_sync(FULLM, xa.z, src);
        float a3 = __shfl_sync(FULLM, xa.w, src);
        float b0 = __shfl_sync(FULLM, xb.x, src);
        float b1 = __shfl_sync(FULLM, xb.y, src);
        float b2 = __shfl_sync(FULLM, xb.z, src);
        float b3 = __shfl_sync(FULLM, xb.w, src);
        float aarr[4] = {a0, a1, a2, a3};
        float barr[4] = {b0, b1, b2, b3};
#pragma unroll
        for (int c = 0; c < 4; c++) {
            ulonglong2 w = *(const ulonglong2*)(Ws + ((kk * 4 + c) * CH + c4));
            unsigned long long x2a = pk2(aarr[c]);
            unsigned long long x2b = pk2(barr[c]);
            fma2(ta01, x2a, w.x);
            fma2(ta23, x2a, w.y);
            fma2(tb01, x2b, w.x);
            fma2(tb23, x2b, w.y);
        }
    }
    float2 p;
    p = upk(ta01); fa[0] = p.x; fa[1] = p.y;
    p = upk(ta23); fa[2] = p.x; fa[3] = p.y;
    p = upk(tb01); fb[0] = p.x; fb[1] = p.y;
    p = upk(tb23); fb[2] = p.x; fb[3] = p.y;
}

// broadcast node n's t to all lanes (owner group holds it, others contribute 0)
__device__ __forceinline__ void bcast4(const float fa[4], const float fb[4],
                                       int n, int grp, float u[4]) {
    bool own = (n >> 1) == grp;
#pragma unroll
    for (int c = 0; c < 4; c++) {
        float v = own ? ((n & 1) ? fb[c] : fa[c]) : 0.f;
        u[c] = v + __shfl_xor_sync(FULLM, v, 16);
    }
}

// scatter t (64 ch across 16 lanes) to node v's hyperedges; 2 edges/iter via groups
__device__ __forceinline__ void scatter_node(float* __restrict__ dst, int v,
                                             int grp, int c4, const float u[4]) {
    int beg = g_rowptr[v], deg = g_rowptr[v + 1] - beg;
    for (int j = grp; j < deg; j += 2) {
        int e = g_csr[beg + j];
        red4(dst + (long)e * CH + c4, u[0], u[1], u[2], u[3]);
    }
}

// gather scaled messages into h = relu(dinv * sum); all lanes end with full h[c4..]
__device__ __forceinline__ void gather_node(const float* __restrict__ src, int v,
                                            int grp, int c4, float h[4]) {
    int beg = g_rowptr[v], deg = g_rowptr[v + 1] - beg;
    float4 acc = make_float4(0.f, 0.f, 0.f, 0.f);
    for (int j = grp; j < deg; j += 2) {
        int e = g_csr[beg + j];
        float4 mv = *(const float4*)(src + (long)e * CH + c4);
        acc.x += mv.x; acc.y += mv.y; acc.z += mv.z; acc.w += mv.w;
    }
    acc.x += __shfl_xor_sync(FULLM, acc.x, 16);
    acc.y += __shfl_xor_sync(FULLM, acc.y, 16);
    acc.z += __shfl_xor_sync(FULLM, acc.z, 16);
    acc.w += __shfl_xor_sync(FULLM, acc.w, 16);
    float di = g_dinv[v];
    h[0] = fmaxf(di * acc.x, 0.f);
    h[1] = fmaxf(di * acc.y, 0.f);
    h[2] = fmaxf(di * acc.z, 0.f);
    h[3] = fmaxf(di * acc.w, 0.f);
}

// ---------------- conv1 pass A: t = xW1+b1, scatter to m ----------------
__global__ void __launch_bounds__(256) k_conv_a(const float* __restrict__ x,
                                                const float* __restrict__ W,
                                                const float* __restrict__ b) {
    __shared__ __align__(16) float Ws[CH * CH];
    __shared__ float bs[CH];
    for (int i = threadIdx.x; i < CH * CH; i += 256) Ws[i] = W[i];
    if (threadIdx.x < CH) bs[threadIdx.x] = b[threadIdx.x];
    __syncthreads();

    int lane = threadIdx.x & 31;
    int warp = blockIdx.x * 8 + (threadIdx.x >> 5);
    int base = warp * 4;
    if (base >= N_NODES) return;   // N_NODES % 4 == 0 -> all 4 nodes valid
    int grp = lane >> 4, c4 = (lane & 15) * 4;
    int va = base + grp * 2, vb = va + 1;

    float4 xa = *(const float4*)(x + (long)va * CH + c4);
    float4 xb = *(const float4*)(x + (long)vb * CH + c4);
    float fa[4], fb[4];
    matvec4(xa, xb, Ws, bs, grp, c4, fa, fb);

#pragma unroll
    for (int n = 0; n < 4; n++) {
        float u[4];
        bcast4(fa, fb, n, grp, u);
        scatter_node(g_m, base + n, grp, c4, u);
    }
}

// -------- conv1 pass B + conv2 pass A: gather m, relu, h W2+b2, scatter m2 --------
__global__ void __launch_bounds__(256) k_conv_b(const float* __restrict__ W,
                                                const float* __restrict__ b) {
    __shared__ __align__(16) float Ws[CH * CH];
    __shared__ float bs[CH];
    for (int i = threadIdx.x; i < CH * CH; i += 256) Ws[i] = W[i];
    if (threadIdx.x < CH) bs[threadIdx.x] = b[threadIdx.x];
    __syncthreads();

    int lane = threadIdx.x & 31;
    int warp = blockIdx.x * 8 + (threadIdx.x >> 5);
    int base = warp * 4;
    if (base >= N_NODES) return;
    int grp = lane >> 4, c4 = (lane & 15) * 4;

    float4 ha = make_float4(0.f, 0.f, 0.f, 0.f);
    float4 hb = ha;
#pragma unroll
    for (int n = 0; n < 4; n++) {
        float h[4];
        gather_node(g_m, base + n, grp, c4, h);
        if ((n >> 1) == grp) {
            if (n & 1) { hb.x = h[0]; hb.y = h[1]; hb.z = h[2]; hb.w = h[3]; }
            else       { ha.x = h[0]; ha.y = h[1]; ha.z = h[2]; ha.w = h[3]; }
        }
    }

    float fa[4], fb[4];
    matvec4(ha, hb, Ws, bs, grp, c4, fa, fb);

#pragma unroll
    for (int n = 0; n < 4; n++) {
        float u[4];
        bcast4(fa, fb, n, grp, u);
        scatter_node(g_m2, base + n, grp, c4, u);
    }
}

// -------- conv2 pass B + pooling + fc dot --------
__global__ void __launch_bounds__(256) k_conv_c(const int* __restrict__ batch,
                                                const float* __restrict__ Wfc) {
    int lane = threadIdx.x & 31;
    int warp = blockIdx.x * 8 + (threadIdx.x >> 5);
    int base = warp * 4;
    if (base >= N_NODES) return;
    int grp = lane >> 4, c4 = (lane & 15) * 4;
    float4 wf = *(const float4*)(Wfc + c4);

    float acc = 0.f;
    int curg = -1;
#pragma unroll
    for (int n = 0; n < 4; n++) {
        int v = base + n;
        float h[4];
        gather_node(g_m2, v, grp, c4, h);
        // both groups hold the full h -> sum only group 0's partials
        float p = (grp == 0) ? (h[0] * wf.x + h[1] * wf.y + h[2] * wf.z + h[3] * wf.w) : 0.f;
#pragma unroll
        for (int o = 16; o > 0; o >>= 1) p += __shfl_xor_sync(FULLM, p, o);
        if (lane == 0) {
            int g = batch[v];
            if (g != curg) {
                if (curg >= 0) atomicAdd(&g_gsum[curg], acc);
                curg = g;
                acc = 0.f;
            }
            acc += p;
        }
    }
    if (lane == 0 && curg >= 0) atomicAdd(&g_gsum[curg], acc);
}

// ---------------- finalize ----------------
__global__ void k_fin(float* __restrict__ out, const float* __restrict__ bfc) {
    int g = blockIdx.x * blockDim.x + threadIdx.x;
    if (g < N_GRAPHS) {
        float cnt = fmaxf((float)g_gcnt[g], 1.f);
        out[g] = g_gsum[g] / cnt + bfc[0];
    }
}

// ---------------- launch ----------------
extern "C" void kernel_launch(void* const* d_in, const int* in_sizes, int n_in,
                              void* d_out, int out_size) {
    const float* x     = (const float*)d_in[0];
    const int*   eidx  = (const int*)d_in[1];
    const int*   row   = eidx;
    const int*   col   = eidx + N_INC;
    const int*   batch = (const int*)d_in[2];
    const float* W1    = (const float*)d_in[3];
    const float* b1    = (const float*)d_in[4];
    const float* W2    = (const float*)d_in[5];
    const float* b2    = (const float*)d_in[6];
    const float* Wfc   = (const float*)d_in[7];
    const float* bfc   = (const float*)d_in[8];
    float*       out   = (float*)d_out;

    const int NB_INC   = (N_INC + 255) / 256;          // 7813
    const int NB_SCAN  = (N_NODES + 1023) / 1024;      // 489
    const int NB_CONV  = (N_NODES / 4) / 8;            // 15625
    const int NB_SCALE = (N_HEDGES * 16 + 255) / 256;  // 6250

    k_zero<<<1024, 256>>>();
    k_hist<<<NB_INC, 256>>>(row, col, batch);
    k_scan1<<<NB_SCAN, 1024>>>();
    k_scan2<<<1, 512>>>(NB_SCAN);
    k_scan3<<<NB_SCAN, 1024>>>();
    k_fill<<<NB_INC, 256>>>(row, col);
    k_conv_a<<<NB_CONV, 256>>>(x, W1, b1);
    k_scale<<<NB_SCALE, 256>>>(0);
    k_conv_b<<<NB_CONV, 256>>>(W2, b2);
    k_scale<<<NB_SCALE, 256>>>(1);
    k_conv_c<<<NB_CONV, 256>>>(batch, Wfc);
    k_fin<<<2, 256>>>(out, bfc);
}